// round 2
// baseline (speedup 1.0000x reference)
#include <cuda_runtime.h>
#include <cuda_bf16.h>
#include <math.h>

#define NROWS 8192
#define DDIM  128
#define KCHUNK 64

// scratch for intermediate manifolds (allocation-free rule: device globals)
__device__ float g_h[NROWS * DDIM];
__device__ float g_q[NROWS * DDIM];
__device__ float g_k[NROWS * DDIM];

// ---------------------------------------------------------------------------
// Kernel A: out = hybo_linear(X, W, b, log_scale)
// CTA tile: 64 rows x 128 cols, 256 threads, thread tile 4 rows x 8 cols.
// Static smem only (48KB exactly): WsT chunk [64][128] + x chunk [64][64],
// K processed in two 64-wide chunks. WsT buffer is reused as the y-tile
// staging area for the epilogue. No cudaFuncSetAttribute needed.
// SRC: 0 = first input x, 1 = g_h.  DST: 0 = g_h, 1 = g_q, 2 = g_k.
// ---------------------------------------------------------------------------
template<int SRC, int DST>
__global__ void __launch_bounds__(256) hybo_kernel(
    const float* __restrict__ Xin, const float* __restrict__ W,
    const float* __restrict__ b, const float* __restrict__ lsc)
{
    __shared__ float sWT[KCHUNK * DDIM];   // 32KB: WsT[kk_local*128 + d]
    __shared__ float sx [64 * KCHUNK];     // 16KB: sx[r*64 + kk_local]

    const float* X = (SRC == 0) ? Xin : g_h;
    float* O = (DST == 0) ? g_h : (DST == 1) ? g_q : g_k;

    const int tid = threadIdx.x;
    const int cg  = tid & 15;        // 16 col groups (8 strided cols each)
    const int rg  = tid >> 4;        // 16 row groups (4 rows each)
    const int r0  = rg * 4;
    const int row_base = blockIdx.x * 64;

    float acc[4][8];
    #pragma unroll
    for (int j = 0; j < 8; j++) {
        float bv = __ldg(&b[cg + 16 * j]);
        #pragma unroll
        for (int r = 0; r < 4; r++) acc[r][j] = bv;
    }

    #pragma unroll
    for (int c = 0; c < 2; c++) {
        // Stage W chunk transposed: W[d][c*64 + kk_local] -> sWT[kk_local][d]
        {
            const int d    = tid & 127;
            const int half = tid >> 7;                  // 0/1
            const float4* W4 = (const float4*)W;
            #pragma unroll
            for (int qq = 0; qq < 8; qq++) {
                float4 wv = W4[d * 32 + c * 16 + half * 8 + qq];
                int kk = half * 32 + qq * 4;
                sWT[(kk + 0) * DDIM + d] = wv.x;
                sWT[(kk + 1) * DDIM + d] = wv.y;
                sWT[(kk + 2) * DDIM + d] = wv.z;
                sWT[(kk + 3) * DDIM + d] = wv.w;
            }
        }
        // Stage x chunk: sx[r][kk_local] = X[row_base+r][c*64 + kk_local]
        {
            const float4* X4 = (const float4*)X;
            float4* sx4 = (float4*)sx;
            #pragma unroll
            for (int i = 0; i < 4; i++) {
                int idx = i * 256 + tid;                // 1024 float4 total
                int r   = idx >> 4;
                int q   = idx & 15;
                sx4[idx] = X4[(size_t)(row_base + r) * 32 + c * 16 + q];
            }
        }
        __syncthreads();

        #pragma unroll 4
        for (int kk = 0; kk < KCHUNK; kk++) {
            float a0 = sx[(r0 + 0) * KCHUNK + kk];
            float a1 = sx[(r0 + 1) * KCHUNK + kk];
            float a2 = sx[(r0 + 2) * KCHUNK + kk];
            float a3 = sx[(r0 + 3) * KCHUNK + kk];
            #pragma unroll
            for (int j = 0; j < 8; j++) {
                float w = sWT[kk * DDIM + cg + 16 * j]; // broadcast x2, no conflict
                acc[0][j] += a0 * w;
                acc[1][j] += a1 * w;
                acc[2][j] += a2 * w;
                acc[3][j] += a3 * w;
            }
        }
        __syncthreads();
    }

    // Dump y tile into sWT (reused as ys[64][128])
    float* ys = sWT;
    #pragma unroll
    for (int r = 0; r < 4; r++)
        #pragma unroll
        for (int j = 0; j < 8; j++)
            ys[(r0 + r) * DDIM + cg + 16 * j] = acc[r][j];
    __syncthreads();

    // Epilogue: Lorentz re-projection, 8 warps x 8 rows
    const int w = tid >> 5, lane = tid & 31;
    const float es = expf(__ldg(lsc));
    #pragma unroll
    for (int rr = 0; rr < 8; rr++) {
        int r = w * 8 + rr;
        float v0 = ys[r * DDIM + lane];
        float v1 = ys[r * DDIM + lane + 32];
        float v2 = ys[r * DDIM + lane + 64];
        float v3 = ys[r * DDIM + lane + 96];
        float part = v1 * v1 + v2 * v2 + v3 * v3;
        if (lane != 0) part += v0 * v0;          // exclude y[0] (time logit)
        #pragma unroll
        for (int off = 16; off; off >>= 1)
            part += __shfl_xor_sync(0xffffffffu, part, off);
        float y0 = __shfl_sync(0xffffffffu, v0, 0);
        float t  = 1.0f / (1.0f + expf(-y0)) * es + 1.1f;
        float sq = fmaxf(part, 1e-8f);
        float st = sqrtf((t * t - 1.0f) / sq);
        size_t rowg = (size_t)(row_base + r) * DDIM;
        O[rowg + lane]      = (lane == 0) ? t : v0 * st;
        O[rowg + lane + 32] = v1 * st;
        O[rowg + lane + 64] = v2 * st;
        O[rowg + lane + 96] = v3 * st;
    }
}

// ---------------------------------------------------------------------------
// Kernel B: fused sparse attention + aggregation + normalization.
// One CTA per output row n. 8 warps; warp w owns adj columns [w*1024,(w+1)*1024).
// For each nonzero adj[n,m]: warp-cooperative 128-d dot (q time negated so the
// Lorentz inner product is a single dot), sigmoid, axpy of h[m] into per-warp
// register accumulators. Fixed traversal/reduction order => deterministic.
// ---------------------------------------------------------------------------
__global__ void __launch_bounds__(256) spmm_kernel(
    const float* __restrict__ adj,
    const float* __restrict__ ab_p, const float* __restrict__ as_p,
    float* __restrict__ O)
{
    const int n    = blockIdx.x;
    const int w    = threadIdx.x >> 5;
    const int lane = threadIdx.x & 31;

    const float4* Q4 = (const float4*)g_q;
    const float4* K4 = (const float4*)g_k;
    const float4* H4 = (const float4*)g_h;

    const float att_bias = __ldg(ab_p);
    const float inv_as   = 1.0f / __ldg(as_p);

    float4 qv = Q4[n * 32 + lane];
    if (lane == 0) qv.x = -qv.x;     // fold the -q0*k0 term into the dot

    float4 accv = make_float4(0.f, 0.f, 0.f, 0.f);
    const float4* adj4 = (const float4*)(adj + (size_t)n * 8192);

    #pragma unroll 1
    for (int it = 0; it < 8; it++) {
        float4 av = adj4[w * 256 + it * 32 + lane];
        int base = w * 1024 + it * 128;
        #pragma unroll
        for (int c = 0; c < 4; c++) {
            float vc = (c == 0) ? av.x : (c == 1) ? av.y : (c == 2) ? av.z : av.w;
            unsigned mask = __ballot_sync(0xffffffffu, vc != 0.0f);
            while (mask) {                       // uniform across warp
                int bpos = __ffs(mask) - 1;
                mask &= mask - 1;
                int m = base + 4 * bpos + c;
                float aval = __shfl_sync(0xffffffffu, vc, bpos);
                float4 kv = K4[m * 32 + lane];
                float4 hv = H4[m * 32 + lane];
                float p = kv.x * qv.x + kv.y * qv.y + kv.z * qv.z + kv.w * qv.w;
                #pragma unroll
                for (int off = 16; off; off >>= 1)
                    p += __shfl_xor_sync(0xffffffffu, p, off);
                float logit = (2.0f + 2.0f * p) * inv_as + att_bias;
                float sg = 1.0f / (1.0f + expf(-logit));
                float wt = aval * sg;
                accv.x += wt * hv.x; accv.y += wt * hv.y;
                accv.z += wt * hv.z; accv.w += wt * hv.w;
            }
        }
    }

    __shared__ float4 accsh[8][32];
    accsh[w][lane] = accv;
    __syncthreads();

    if (w == 0) {
        float4 s = accsh[0][lane];
        #pragma unroll
        for (int ww = 1; ww < 8; ww++) {         // fixed order: deterministic
            float4 t = accsh[ww][lane];
            s.x += t.x; s.y += t.y; s.z += t.z; s.w += t.w;
        }
        float part = s.x * s.x + s.y * s.y + s.z * s.z + s.w * s.w;
        #pragma unroll
        for (int off = 16; off; off >>= 1)
            part += __shfl_xor_sync(0xffffffffu, part, off);
        float s0 = __shfl_sync(0xffffffffu, s.x, 0);
        // l_inner = -s0^2 + (sum_all - s0^2)  ->  |l_inner| = |sum_all - 2 s0^2|
        float v  = fabsf(part - 2.0f * s0 * s0);
        float rd = rsqrtf(fmaxf(v, 1e-6f));
        float4 o = make_float4(s.x * rd, s.y * rd, s.z * rd, s.w * rd);
        ((float4*)O)[n * 32 + lane] = o;
    }
}

// ---------------------------------------------------------------------------
// kernel_launch: ONLY kernel launches — no attribute calls, no symbol lookups,
// nothing that could upset graph capture or the enforcement scan.
// ---------------------------------------------------------------------------
extern "C" void kernel_launch(void* const* d_in, const int* in_sizes, int n_in,
                              void* d_out, int out_size) {
    const float* x     = (const float*)d_in[0];
    const float* adj   = (const float*)d_in[1];
    const float* W_lin = (const float*)d_in[2];
    const float* b_lin = (const float*)d_in[3];
    const float* s_lin = (const float*)d_in[4];
    const float* W_q   = (const float*)d_in[5];
    const float* b_q   = (const float*)d_in[6];
    const float* s_q   = (const float*)d_in[7];
    const float* W_k   = (const float*)d_in[8];
    const float* b_k   = (const float*)d_in[9];
    const float* s_k   = (const float*)d_in[10];
    const float* att_b = (const float*)d_in[11];
    const float* att_s = (const float*)d_in[12];
    float* out = (float*)d_out;

    hybo_kernel<0, 0><<<NROWS / 64, 256>>>(x,       W_lin, b_lin, s_lin);
    hybo_kernel<1, 1><<<NROWS / 64, 256>>>(nullptr, W_q,   b_q,   s_q);
    hybo_kernel<1, 2><<<NROWS / 64, 256>>>(nullptr, W_k,   b_k,   s_k);
    spmm_kernel<<<NROWS, 256>>>(adj, att_b, att_s, out);
}